// round 2
// baseline (speedup 1.0000x reference)
#include <cuda_runtime.h>
#include <math_constants.h>

// Problem constants (fixed by setup_inputs): B=16, Hr*Wr=R=4096, Hq*Wq=Q=1024
#define R 4096
#define Q 1024
#define GROUP 4                 // batches per L2-resident group (4*16.75MB = 67MB < 126MB L2)
#define RCHUNK 16               // rows per pass1 block
#define CPB (R / RCHUNK)        // 256 chunk-partials per batch column
#define GCOLS (GROUP * Q)       // 4096 columns per group

// Scratch (reused across sequential groups):
__device__ float g_part[CPB * GCOLS];      // 4 MB partial column sums
__device__ float g_creflog[GROUP * Q];     // 16 KB log column sums

// ---------------------------------------------------------------------------
// Pass 1: partial column sums of exp(ar*x) over 16-row chunks of one group.
// grid = gb * CPB blocks, 256 threads; thread t owns float4 column t.
// Reads populate L2 (default .ca policy) for pass2 reuse.
// ---------------------------------------------------------------------------
__global__ __launch_bounds__(256) void qatm_pass1(
    const float* __restrict__ x, const float* __restrict__ coef_ref, int b0)
{
    const int b_local = blockIdx.x >> 8;          // / CPB
    const int c       = blockIdx.x & (CPB - 1);
    const int t       = threadIdx.x;

    const float ar = coef_ref[0];

    const float4* p = reinterpret_cast<const float4*>(
        x + ((size_t)(b0 + b_local) * R + (size_t)c * RCHUNK) * Q) + t;

    float4 acc = make_float4(0.f, 0.f, 0.f, 0.f);

    #pragma unroll 1
    for (int r = 0; r < RCHUNK; r += 4) {
        float4 v0 = p[0 * (Q / 4)];
        float4 v1 = p[1 * (Q / 4)];
        float4 v2 = p[2 * (Q / 4)];
        float4 v3 = p[3 * (Q / 4)];
        p += 4 * (Q / 4);
        acc.x += __expf(ar * v0.x); acc.y += __expf(ar * v0.y);
        acc.z += __expf(ar * v0.z); acc.w += __expf(ar * v0.w);
        acc.x += __expf(ar * v1.x); acc.y += __expf(ar * v1.y);
        acc.z += __expf(ar * v1.z); acc.w += __expf(ar * v1.w);
        acc.x += __expf(ar * v2.x); acc.y += __expf(ar * v2.y);
        acc.z += __expf(ar * v2.z); acc.w += __expf(ar * v2.w);
        acc.x += __expf(ar * v3.x); acc.y += __expf(ar * v3.y);
        acc.z += __expf(ar * v3.z); acc.w += __expf(ar * v3.w);
    }

    float4* outp = reinterpret_cast<float4*>(
        g_part + (size_t)c * GCOLS + (size_t)b_local * Q);
    outp[t] = acc;
}

// ---------------------------------------------------------------------------
// Reduce CPB chunk partials per column, take log -> g_creflog.
// 4 threads per column, 64 columns per block. All reads are fresh L2 hits.
// ---------------------------------------------------------------------------
__global__ __launch_bounds__(256) void qatm_colreduce()
{
    __shared__ float s_red[256];
    const int t    = threadIdx.x;
    const int col  = blockIdx.x * 64 + (t & 63);
    const int part = t >> 6;                      // 0..3, 64 chunks each

    float s = 0.f;
    const float* p = g_part + (size_t)(part * 64) * GCOLS + col;
    #pragma unroll 8
    for (int c = 0; c < 64; ++c)
        s += p[(size_t)c * GCOLS];

    s_red[t] = s;
    __syncthreads();
    if (part == 0) {
        float tot = s_red[t] + s_red[t + 64] + s_red[t + 128] + s_red[t + 192];
        g_creflog[col] = __logf(tot);
    }
}

// ---------------------------------------------------------------------------
// Pass 2: one warp per row. Single read of the 4KB row computes
//   s = sum_q exp(aq*x)   and   m = max_q ((ar+aq)*x - Cref[q])
// out[row] = exp(0.5*(m - log s)). x read with __ldcs (last touch).
// ---------------------------------------------------------------------------
__global__ __launch_bounds__(256) void qatm_pass2(
    const float* __restrict__ x,
    const float* __restrict__ coef_ref,
    const float* __restrict__ coef_qry,
    float* __restrict__ out, int b0)
{
    __shared__ __align__(16) float s_clog[Q];

    const int wid      = threadIdx.x >> 5;
    const int lane     = threadIdx.x & 31;
    const int row0     = blockIdx.x * 8;          // local row within group
    const int b_local  = row0 >> 12;              // / R

    // Stage Cref[b_local][*] into shared memory
    const float4* cl = reinterpret_cast<const float4*>(g_creflog + (size_t)b_local * Q);
    float4* sc = reinterpret_cast<float4*>(s_clog);
    sc[threadIdx.x] = cl[threadIdx.x];            // 256 threads == Q/4
    __syncthreads();

    const float ar = coef_ref[0];
    const float aq = coef_qry[0];
    const float cc = ar + aq;

    const size_t row = (size_t)b0 * R + row0 + wid;
    const float4* p = reinterpret_cast<const float4*>(x + row * Q);

    float s = 0.f;
    float m = -CUDART_INF_F;

    #pragma unroll
    for (int it = 0; it < 8; ++it) {
        int q4 = it * 32 + lane;
        float4 v = __ldcs(p + q4);                // evict-first: last touch
        float4 cg = sc[q4];
        s += __expf(aq * v.x);
        s += __expf(aq * v.y);
        s += __expf(aq * v.z);
        s += __expf(aq * v.w);
        float m0 = fmaxf(fmaf(cc, v.x, -cg.x), fmaf(cc, v.y, -cg.y));
        float m1 = fmaxf(fmaf(cc, v.z, -cg.z), fmaf(cc, v.w, -cg.w));
        m = fmaxf(m, fmaxf(m0, m1));
    }

    #pragma unroll
    for (int o = 16; o > 0; o >>= 1) {
        s += __shfl_xor_sync(0xFFFFFFFFu, s, o);
        m = fmaxf(m, __shfl_xor_sync(0xFFFFFFFFu, m, o));
    }

    if (lane == 0)
        out[row] = __expf(0.5f * (m - __logf(s)));
}

// ---------------------------------------------------------------------------
extern "C" void kernel_launch(void* const* d_in, const int* in_sizes, int n_in,
                              void* d_out, int out_size)
{
    const float* x  = (const float*)d_in[0];
    const float* cr = (const float*)d_in[1];
    const float* cq = (const float*)d_in[2];
    float* out = (float*)d_out;

    const int B = in_sizes[0] / (R * Q);          // 16

    for (int b0 = 0; b0 < B; b0 += GROUP) {
        int gb = (B - b0 < GROUP) ? (B - b0) : GROUP;
        qatm_pass1<<<gb * CPB, 256>>>(x, cr, b0);
        qatm_colreduce<<<gb * Q / 64, 256>>>();
        qatm_pass2<<<gb * R / 8, 256>>>(x, cr, cq, out, b0);
    }
}